// round 4
// baseline (speedup 1.0000x reference)
#include <cuda_runtime.h>
#include <cuda_fp16.h>
#include <cstdint>

#define DI __device__ __forceinline__

// ---------------- problem constants (fixed shapes) ----------------
constexpr int NTOK   = 4096;   // B*S = 2*2048
constexpr int DMODEL = 1024;
constexpr int DFF    = 4096;
constexpr int HH     = 32;

// ---------------- scratch (device globals; no allocs allowed) ----------------
__device__ __align__(16) __half g_xh  [NTOK * DMODEL];      // 8 MB
__device__ __align__(16) __half g_w1ah[DFF  * DMODEL];      // 8 MB
__device__ __align__(16) __half g_w1bh[DFF  * DMODEL];      // 8 MB
__device__ __align__(16) __half g_w2h [DMODEL * DFF];       // 8 MB
__device__ __align__(16) __half g_act [(size_t)NTOK * DFF]; // 32 MB

// ---------------- PTX helpers ----------------
DI uint32_t s2u(const void* p) {
    uint32_t a;
    asm("{ .reg .u64 t; cvta.to.shared.u64 t, %1; cvt.u32.u64 %0, t; }"
        : "=r"(a) : "l"(p));
    return a;
}

#define CP_COMMIT() asm volatile("cp.async.commit_group;" ::: "memory")
#define CP_WAIT_2() asm volatile("cp.async.wait_group 2;" ::: "memory")
#define CP_WAIT_1() asm volatile("cp.async.wait_group 1;" ::: "memory")

DI void cp16(uint32_t sdst, const void* gsrc) {
    asm volatile("cp.async.cg.shared.global [%0], [%1], 16;"
                 :: "r"(sdst), "l"(__cvta_generic_to_global(gsrc)) : "memory");
}

DI void ldsm4(uint32_t r[4], uint32_t addr) {
    asm volatile("ldmatrix.sync.aligned.m8n8.x4.shared.b16 {%0,%1,%2,%3}, [%4];"
                 : "=r"(r[0]), "=r"(r[1]), "=r"(r[2]), "=r"(r[3]) : "r"(addr));
}

DI void mma16816(float c[4], const uint32_t a[4], uint32_t b0, uint32_t b1) {
    asm volatile(
        "mma.sync.aligned.m16n8k16.row.col.f32.f16.f16.f32 "
        "{%0,%1,%2,%3}, {%4,%5,%6,%7}, {%8,%9}, {%0,%1,%2,%3};"
        : "+f"(c[0]), "+f"(c[1]), "+f"(c[2]), "+f"(c[3])
        : "r"(a[0]), "r"(a[1]), "r"(a[2]), "r"(a[3]), "r"(b0), "r"(b1));
}

// ---- packed f32x2 ----
DI uint64_t pk64(float lo, float hi) {
    uint64_t r; asm("mov.b64 %0, {%1, %2};" : "=l"(r) : "f"(lo), "f"(hi)); return r;
}
DI void upk64(float& lo, float& hi, uint64_t v) {
    asm("mov.b64 {%0, %1}, %2;" : "=f"(lo), "=f"(hi) : "l"(v));
}
DI uint64_t fma2(uint64_t a, uint64_t b, uint64_t c) {
    uint64_t d; asm("fma.rn.f32x2 %0, %1, %2, %3;" : "=l"(d) : "l"(a), "l"(b), "l"(c));
    return d;
}
DI uint64_t add2(uint64_t a, uint64_t b) {
    uint64_t d; asm("add.rn.f32x2 %0, %1, %2;" : "=l"(d) : "l"(a), "l"(b));
    return d;
}

// SW128 swizzled address inside a 128-row x 128-byte tile.
DI uint32_t tile_addr(uint32_t base, int row, int chunk) {
    return base + row * 128 + (((chunk) ^ (row & 7)) << 4);
}

// Load a 128-row x 64-fp16 (128B/row) tile into SW128-swizzled SMEM via cp.async.
template <int NT>
DI void load_tile(uint32_t sdst, const __half* g, int row0, int col0, int ldk, int tid) {
#pragma unroll
    for (int i = 0; i < 1024 / NT; ++i) {
        int idx = tid + i * NT;
        int r = idx >> 3, c = idx & 7;
        uint32_t off = (uint32_t)(r * 128) + (uint32_t)(((c ^ (r & 7)) << 4));
        cp16(sdst + off, g + (size_t)(row0 + r) * ldk + col0 + c * 8);
    }
}

DI uint32_t pack2(float a, float b) {
    __half2 h = __floats2half2_rn(a, b);
    return reinterpret_cast<uint32_t&>(h);
}

// ---------------- SMEM layouts ----------------
constexpr int G1_STAGE  = 49152;                  // A(16K)+Ba(16K)+Bb(16K)
constexpr int G1_NSTG   = 4;
constexpr int G1_PAR    = G1_NSTG * G1_STAGE;     // 196608
constexpr int SMEM1_TOTAL = G1_PAR + 2176;        // 198784
constexpr int G2_STAGE  = 32768;                  // A(16K)+B(16K)
constexpr int G2_NSTG   = 3;
constexpr int G2_PAR    = G2_NSTG * G2_STAGE;     // 98304
constexpr int SMEM2_TOTAL = G2_PAR + 512;         // 98816 (occ 2)

constexpr uint64_t ABSMASK2 = 0x7FFFFFFF7FFFFFFFULL;

// =====================================================================
// Kernel 0: fp32 -> fp16 conversion of x, W1a, W1b, W2
// =====================================================================
__global__ void __launch_bounds__(256) convert_kernel(
    const float4* __restrict__ x, const float4* __restrict__ w1a,
    const float4* __restrict__ w1b, const float4* __restrict__ w2)
{
    int i = blockIdx.x * 256 + threadIdx.x;   // 4096*256 = 2^20 float4s per array
    float4 v;
    v = x[i];   ((uint2*)g_xh)[i]   = make_uint2(pack2(v.x, v.y), pack2(v.z, v.w));
    v = w1a[i]; ((uint2*)g_w1ah)[i] = make_uint2(pack2(v.x, v.y), pack2(v.z, v.w));
    v = w1b[i]; ((uint2*)g_w1bh)[i] = make_uint2(pack2(v.x, v.y), pack2(v.z, v.w));
    v = w2[i];  ((uint2*)g_w2h)[i]  = make_uint2(pack2(v.x, v.y), pack2(v.z, v.w));
}

// =====================================================================
// Kernel 1: fused GEMM1 (a & b projections) + InnerNet -> fp16 act
// CTA tile 128 tokens x 128 ff. 256 threads, 2x4 warp grid, 64x32 warp tiles.
// 4-stage cp.async pipeline, single __syncthreads per K-chunk.
// =====================================================================
__global__ void __launch_bounds__(256) gemm1_kernel(
    const float* __restrict__ b1a, const float* __restrict__ b1b,
    const float* __restrict__ wi1, const float* __restrict__ bi1,
    const float* __restrict__ wi2, const float* __restrict__ bi2)
{
    extern __shared__ char smem[];
    uint32_t sb = s2u(smem);
    int tid = threadIdx.x, lane = tid & 31, wid = tid >> 5;
    int wm = wid >> 2, wn = wid & 3;          // 2x4 warp grid, 64x32 tiles
    int f0 = blockIdx.x * 128;                // d_ff tile
    int m0 = blockIdx.y * 128;                // token tile

    // ---- params -> smem ----
    float*    spa = (float*)(smem + G1_PAR);
    float*    spb = (float*)(smem + G1_PAR + 512);
    uint64_t* ph  = (uint64_t*)(smem + G1_PAR + 1024);
    uint64_t* pb2 = (uint64_t*)(smem + G1_PAR + 2048);
    if (tid < 128) { spa[tid] = b1a[f0 + tid]; spb[tid] = b1b[f0 + tid]; }
    else if (tid < 160) {
        int h = tid - 128;
        float w0 = wi1[2 * h], w1 = wi1[2 * h + 1];
        float cb = bi1[h], vh = 0.5f * wi2[h];
        ph[h * 4 + 0] = pk64(w0, w0);
        ph[h * 4 + 1] = pk64(w1, w1);
        ph[h * 4 + 2] = pk64(cb, cb);
        ph[h * 4 + 3] = pk64(vh, vh);
    } else if (tid == 160) {
        float v = bi2[0]; pb2[0] = pk64(v, v);
    }

    // ---- prologue: prefetch chunks 0..2 into stages 0..2 ----
#pragma unroll
    for (int s = 0; s < 3; ++s) {
        uint32_t st = sb + s * G1_STAGE;
        int col = s * 64;
        load_tile<256>(st,         g_xh,   m0, col, DMODEL, tid);
        load_tile<256>(st + 16384, g_w1ah, f0, col, DMODEL, tid);
        load_tile<256>(st + 32768, g_w1bh, f0, col, DMODEL, tid);
        CP_COMMIT();
    }

    float acca[4][4][4], accb[4][4][4];
#pragma unroll
    for (int i = 0; i < 4; ++i)
#pragma unroll
        for (int j = 0; j < 4; ++j)
#pragma unroll
            for (int e = 0; e < 4; ++e) { acca[i][j][e] = 0.f; accb[i][j][e] = 0.f; }

    const int lr = lane & 15, lc = lane >> 4;
    constexpr int NCH = DMODEL / 64;          // 16 K-chunks
    for (int c = 0; c < NCH; ++c) {
        CP_WAIT_2();          // chunk c resident (c+1, c+2 may be in flight)
        __syncthreads();      // all warps finished reading stage (c-1)%4
        if (c + 3 < NCH) {
            uint32_t st = sb + ((c + 3) & 3) * G1_STAGE;
            int col = (c + 3) * 64;
            load_tile<256>(st,         g_xh,   m0, col, DMODEL, tid);
            load_tile<256>(st + 16384, g_w1ah, f0, col, DMODEL, tid);
            load_tile<256>(st + 32768, g_w1bh, f0, col, DMODEL, tid);
        }
        CP_COMMIT();

        uint32_t ab  = sb + (c & 3) * G1_STAGE;
        uint32_t bab = ab + 16384;
        uint32_t bbb = ab + 32768;
#pragma unroll
        for (int ks = 0; ks < 4; ++ks) {
            uint32_t afr[4][4], bfa[2][4], bfb[2][4];
#pragma unroll
            for (int i = 0; i < 4; ++i)
                ldsm4(afr[i], tile_addr(ab, wm * 64 + i * 16 + lr, ks * 2 + lc));
#pragma unroll
            for (int q = 0; q < 2; ++q) {
                ldsm4(bfa[q], tile_addr(bab, wn * 32 + q * 16 + lr, ks * 2 + lc));
                ldsm4(bfb[q], tile_addr(bbb, wn * 32 + q * 16 + lr, ks * 2 + lc));
            }
#pragma unroll
            for (int i = 0; i < 4; ++i)
#pragma unroll
                for (int j = 0; j < 4; ++j) {
                    int q = j >> 1, s = j & 1;
                    mma16816(acca[i][j], afr[i], bfa[q][s], bfa[q][s + 2]);
                    mma16816(accb[i][j], afr[i], bfb[q][s], bfb[q][s + 2]);
                }
        }
    }

    // ---- epilogue: bias + InnerNet (packed f32x2), write fp16 act ----
    // relu(t)*v == (t + |t|) * (v/2), exact in fp32.
    const uint64_t ACC0 = pb2[0];
    const int g = lane >> 2, tg = lane & 3;
#pragma unroll
    for (int i = 0; i < 4; ++i) {
        uint64_t A[8], B[8], ACC[8];
#pragma unroll
        for (int j = 0; j < 4; ++j) {
            int cb = wn * 32 + j * 8 + tg * 2;
            uint64_t ba = *(const uint64_t*)&spa[cb];
            uint64_t bb = *(const uint64_t*)&spb[cb];
            A[j * 2]     = add2(pk64(acca[i][j][0], acca[i][j][1]), ba);
            A[j * 2 + 1] = add2(pk64(acca[i][j][2], acca[i][j][3]), ba);
            B[j * 2]     = add2(pk64(accb[i][j][0], accb[i][j][1]), bb);
            B[j * 2 + 1] = add2(pk64(accb[i][j][2], accb[i][j][3]), bb);
            ACC[j * 2] = ACC0; ACC[j * 2 + 1] = ACC0;
        }
#pragma unroll 1
        for (int h = 0; h < HH; ++h) {
            uint64_t W0 = ph[h * 4 + 0], W1 = ph[h * 4 + 1];
            uint64_t CB = ph[h * 4 + 2], VH = ph[h * 4 + 3];
#pragma unroll
            for (int p = 0; p < 8; ++p) {
                uint64_t t = fma2(A[p], W0, fma2(B[p], W1, CB));
                uint64_t u = add2(t, t & ABSMASK2);
                ACC[p] = fma2(u, VH, ACC[p]);
            }
        }
        int rowg = m0 + wm * 64 + i * 16 + g;
#pragma unroll
        for (int j = 0; j < 4; ++j) {
            int col = f0 + wn * 32 + j * 8 + tg * 2;
            float x0, x1, y0, y1;
            upk64(x0, x1, ACC[j * 2]);
            upk64(y0, y1, ACC[j * 2 + 1]);
            *(uint32_t*)&g_act[(size_t)rowg * DFF + col]       = pack2(x0, x1);
            *(uint32_t*)&g_act[(size_t)(rowg + 8) * DFF + col] = pack2(y0, y1);
        }
    }
}

// =====================================================================
// Kernel 2: out = act @ W2^T + b2   (fp16 in, fp32 out)
// CTA tile 128 tokens x 128 d_model. 256 threads, 2x4 warp grid, 64x32 warp tiles.
// 3-stage cp.async pipeline, single __syncthreads per K-chunk, occ 2.
// =====================================================================
__global__ void __launch_bounds__(256) gemm2_kernel(
    const float* __restrict__ b2, float* __restrict__ out)
{
    extern __shared__ char smem[];
    uint32_t sb = s2u(smem);
    int tid = threadIdx.x, lane = tid & 31, wid = tid >> 5;
    int wm = wid >> 2, wn = wid & 3;          // 2x4 warp grid
    int n0 = blockIdx.x * 128;                // d_model tile
    int m0 = blockIdx.y * 128;                // token tile

    float* sp = (float*)(smem + G2_PAR);
    if (tid < 128) sp[tid] = b2[n0 + tid];

#pragma unroll
    for (int s = 0; s < 2; ++s) {
        uint32_t st = sb + s * G2_STAGE;
        load_tile<256>(st,         g_act, m0, s * 64, DFF, tid);
        load_tile<256>(st + 16384, g_w2h, n0, s * 64, DFF, tid);
        CP_COMMIT();
    }

    float acc[4][4][4];
#pragma unroll
    for (int i = 0; i < 4; ++i)
#pragma unroll
        for (int j = 0; j < 4; ++j)
#pragma unroll
            for (int e = 0; e < 4; ++e) acc[i][j][e] = 0.f;

    const int lr = lane & 15, lc = lane >> 4;
    constexpr int NCH = DFF / 64;             // 64 K-chunks
    for (int c = 0; c < NCH; ++c) {
        CP_WAIT_1();          // chunk c resident
        __syncthreads();      // all warps done reading stage (c-1)%3
        if (c + 2 < NCH) {
            uint32_t st = sb + ((c + 2) % 3) * G2_STAGE;
            int col = (c + 2) * 64;
            load_tile<256>(st,         g_act, m0, col, DFF, tid);
            load_tile<256>(st + 16384, g_w2h, n0, col, DFF, tid);
        }
        CP_COMMIT();

        uint32_t ab = sb + (c % 3) * G2_STAGE;
        uint32_t bb = ab + 16384;
#pragma unroll
        for (int ks = 0; ks < 4; ++ks) {
            uint32_t afr[4][4], bf[2][4];
#pragma unroll
            for (int i = 0; i < 4; ++i)
                ldsm4(afr[i], tile_addr(ab, wm * 64 + i * 16 + lr, ks * 2 + lc));
#pragma unroll
            for (int q = 0; q < 2; ++q)
                ldsm4(bf[q], tile_addr(bb, wn * 32 + q * 16 + lr, ks * 2 + lc));
#pragma unroll
            for (int i = 0; i < 4; ++i)
#pragma unroll
                for (int j = 0; j < 4; ++j) {
                    int q = j >> 1, s = j & 1;
                    mma16816(acc[i][j], afr[i], bf[q][s], bf[q][s + 2]);
                }
        }
    }

    const int g = lane >> 2, tg = lane & 3;
#pragma unroll
    for (int i = 0; i < 4; ++i) {
        int rowg = m0 + wm * 64 + i * 16 + g;
#pragma unroll
        for (int j = 0; j < 4; ++j) {
            int cb = wn * 32 + j * 8 + tg * 2;
            float2 v0 = make_float2(acc[i][j][0] + sp[cb], acc[i][j][1] + sp[cb + 1]);
            float2 v1 = make_float2(acc[i][j][2] + sp[cb], acc[i][j][3] + sp[cb + 1]);
            *(float2*)&out[(size_t)rowg * DMODEL + n0 + cb]       = v0;
            *(float2*)&out[(size_t)(rowg + 8) * DMODEL + n0 + cb] = v1;
        }
    }
}

// =====================================================================
// launch
// =====================================================================
extern "C" void kernel_launch(void* const* d_in, const int* in_sizes, int n_in,
                              void* d_out, int out_size)
{
    const float* x   = (const float*)d_in[0];
    const float* W1a = (const float*)d_in[1];
    const float* b1a = (const float*)d_in[2];
    const float* W1b = (const float*)d_in[3];
    const float* b1b = (const float*)d_in[4];
    const float* Wi1 = (const float*)d_in[5];
    const float* bi1 = (const float*)d_in[6];
    const float* Wi2 = (const float*)d_in[7];
    const float* bi2 = (const float*)d_in[8];
    const float* W2  = (const float*)d_in[9];
    const float* b2  = (const float*)d_in[10];
    float* out = (float*)d_out;

    cudaFuncSetAttribute(gemm1_kernel, cudaFuncAttributeMaxDynamicSharedMemorySize, SMEM1_TOTAL);
    cudaFuncSetAttribute(gemm2_kernel, cudaFuncAttributeMaxDynamicSharedMemorySize, SMEM2_TOTAL);

    convert_kernel<<<4096, 256>>>((const float4*)x, (const float4*)W1a,
                                  (const float4*)W1b, (const float4*)W2);
    gemm1_kernel<<<dim3(DFF / 128, NTOK / 128), 256, SMEM1_TOTAL>>>(b1a, b1b, Wi1, bi1, Wi2, bi2);
    gemm2_kernel<<<dim3(DMODEL / 128, NTOK / 128), 256, SMEM2_TOTAL>>>(b2, out);
}

// round 6
// speedup vs baseline: 1.0957x; 1.0957x over previous
#include <cuda_runtime.h>
#include <cuda_fp16.h>
#include <cstdint>

#define DI __device__ __forceinline__

// ---------------- problem constants (fixed shapes) ----------------
constexpr int NTOK   = 4096;   // B*S = 2*2048
constexpr int DMODEL = 1024;
constexpr int DFF    = 4096;
constexpr int HH     = 32;

// ---------------- scratch (device globals; no allocs allowed) ----------------
__device__ __align__(16) __half g_xh  [NTOK * DMODEL];      // 8 MB
__device__ __align__(16) __half g_w1ah[DFF  * DMODEL];      // 8 MB
__device__ __align__(16) __half g_w1bh[DFF  * DMODEL];      // 8 MB
__device__ __align__(16) __half g_w2h [DMODEL * DFF];       // 8 MB
__device__ __align__(16) __half g_act [(size_t)NTOK * DFF]; // 32 MB

// ---------------- PTX helpers ----------------
DI uint32_t s2u(const void* p) {
    uint32_t a;
    asm("{ .reg .u64 t; cvta.to.shared.u64 t, %1; cvt.u32.u64 %0, t; }"
        : "=r"(a) : "l"(p));
    return a;
}

#define CP_COMMIT() asm volatile("cp.async.commit_group;" ::: "memory")
#define CP_WAIT_1() asm volatile("cp.async.wait_group 1;" ::: "memory")

DI void cp16(uint32_t sdst, const void* gsrc) {
    asm volatile("cp.async.cg.shared.global [%0], [%1], 16;"
                 :: "r"(sdst), "l"(__cvta_generic_to_global(gsrc)) : "memory");
}

DI void ldsm4(uint32_t r[4], uint32_t addr) {
    asm volatile("ldmatrix.sync.aligned.m8n8.x4.shared.b16 {%0,%1,%2,%3}, [%4];"
                 : "=r"(r[0]), "=r"(r[1]), "=r"(r[2]), "=r"(r[3]) : "r"(addr));
}

DI void mma16816(float c[4], const uint32_t a[4], uint32_t b0, uint32_t b1) {
    asm volatile(
        "mma.sync.aligned.m16n8k16.row.col.f32.f16.f16.f32 "
        "{%0,%1,%2,%3}, {%4,%5,%6,%7}, {%8,%9}, {%0,%1,%2,%3};"
        : "+f"(c[0]), "+f"(c[1]), "+f"(c[2]), "+f"(c[3])
        : "r"(a[0]), "r"(a[1]), "r"(a[2]), "r"(a[3]), "r"(b0), "r"(b1));
}

// SW128 swizzled address inside a ROWS x 128-byte tile.
DI uint32_t tile_addr(uint32_t base, int row, int chunk) {
    return base + row * 128 + (((chunk) ^ (row & 7)) << 4);
}

// Load a ROWS x 64-fp16 (128B/row) tile into SW128-swizzled SMEM via cp.async.
template <int NT, int ROWS>
DI void load_tile(uint32_t sdst, const __half* g, int row0, int col0, int ldk, int tid) {
#pragma unroll
    for (int i = 0; i < ROWS * 8 / NT; ++i) {
        int idx = tid + i * NT;
        int r = idx >> 3, c = idx & 7;
        uint32_t off = (uint32_t)(r * 128) + (uint32_t)(((c ^ (r & 7)) << 4));
        cp16(sdst + off, g + (size_t)(row0 + r) * ldk + col0 + c * 8);
    }
}

DI uint32_t pack2(float a, float b) {
    __half2 h = __floats2half2_rn(a, b);
    return reinterpret_cast<uint32_t&>(h);
}

// ---------------- SMEM layouts ----------------
// gemm1: stage = A(16K for 128 rows) + Ba(8K for 64 rows) + Bb(8K) = 32K, 3 stages
constexpr int G1_STAGE  = 32768;
constexpr int G1_NSTG   = 3;
constexpr int G1_PAR    = G1_NSTG * G1_STAGE;     // 98304
constexpr int SMEM1_TOTAL = G1_PAR + 2048;        // 100352 -> 2 CTAs/SM fits 227KB
// gemm2: stage = A(16K) + B(16K) = 32K, 3 stages
constexpr int G2_STAGE  = 32768;
constexpr int G2_NSTG   = 3;
constexpr int G2_PAR    = G2_NSTG * G2_STAGE;     // 98304
constexpr int SMEM2_TOTAL = G2_PAR + 512;         // 98816 (occ 2)

// =====================================================================
// Kernel 0: fp32 -> fp16 conversion of x, W1a, W1b, W2
// =====================================================================
__global__ void __launch_bounds__(256) convert_kernel(
    const float4* __restrict__ x, const float4* __restrict__ w1a,
    const float4* __restrict__ w1b, const float4* __restrict__ w2)
{
    int i = blockIdx.x * 256 + threadIdx.x;   // 4096*256 = 2^20 float4s per array
    float4 v;
    v = x[i];   ((uint2*)g_xh)[i]   = make_uint2(pack2(v.x, v.y), pack2(v.z, v.w));
    v = w1a[i]; ((uint2*)g_w1ah)[i] = make_uint2(pack2(v.x, v.y), pack2(v.z, v.w));
    v = w1b[i]; ((uint2*)g_w1bh)[i] = make_uint2(pack2(v.x, v.y), pack2(v.z, v.w));
    v = w2[i];  ((uint2*)g_w2h)[i]  = make_uint2(pack2(v.x, v.y), pack2(v.z, v.w));
}

// =====================================================================
// Kernel 1: fused GEMM1 (a & b projections) + InnerNet -> fp16 act
// CTA tile 128 tokens x 64 ff. 256 threads, 4x2 warp grid, 32x32 warp tiles.
// 3-stage cp.async pipeline, OCCUPANCY 2: one CTA's FMA-pipe InnerNet epilogue
// overlaps the co-resident CTA's tensor-pipe mainloop.
// =====================================================================
__global__ void __launch_bounds__(256, 2) gemm1_kernel(
    const float* __restrict__ b1a, const float* __restrict__ b1b,
    const float* __restrict__ wi1, const float* __restrict__ bi1,
    const float* __restrict__ wi2, const float* __restrict__ bi2)
{
    extern __shared__ char smem[];
    uint32_t sb = s2u(smem);
    int tid = threadIdx.x, lane = tid & 31, wid = tid >> 5;
    int wm = wid & 3, wn = wid >> 2;          // 4x2 warp grid, 32x32 tiles
    int f0 = blockIdx.x * 64;                 // d_ff tile
    int m0 = blockIdx.y * 128;                // token tile

    // ---- params -> smem ----
    // sp[0..63] bias_a, [64..127] bias_b, [128..191] wi1, [192..223] bi1,
    // [224..255] wi2, [256] bi2
    float* sp = (float*)(smem + G1_PAR);
    if (tid < 64) { sp[tid] = b1a[f0 + tid]; sp[64 + tid] = b1b[f0 + tid]; }
    else if (tid < 128) sp[64 + tid] = wi1[tid - 64];
    else if (tid < 160) { sp[64 + tid] = bi1[tid - 128]; sp[96 + tid] = wi2[tid - 128]; }
    else if (tid == 160) sp[256] = bi2[0];

    // ---- prologue: chunks 0,1 into stages 0,1 ----
#pragma unroll
    for (int s = 0; s < 2; ++s) {
        uint32_t st = sb + s * G1_STAGE;
        int col = s * 64;
        load_tile<256, 128>(st,         g_xh,   m0, col, DMODEL, tid);
        load_tile<256, 64 >(st + 16384, g_w1ah, f0, col, DMODEL, tid);
        load_tile<256, 64 >(st + 24576, g_w1bh, f0, col, DMODEL, tid);
        CP_COMMIT();
    }

    float acca[2][4][4], accb[2][4][4];
#pragma unroll
    for (int i = 0; i < 2; ++i)
#pragma unroll
        for (int j = 0; j < 4; ++j)
#pragma unroll
            for (int e = 0; e < 4; ++e) { acca[i][j][e] = 0.f; accb[i][j][e] = 0.f; }

    const int lr = lane & 15, lc = lane >> 4;
    constexpr int NCH = DMODEL / 64;          // 16 K-chunks
    for (int c = 0; c < NCH; ++c) {
        CP_WAIT_1();          // chunk c resident (c+1 may be in flight)
        __syncthreads();      // all warps finished reading stage (c-1)%3
        if (c + 2 < NCH) {
            uint32_t st = sb + ((c + 2) % 3) * G1_STAGE;
            int col = (c + 2) * 64;
            load_tile<256, 128>(st,         g_xh,   m0, col, DMODEL, tid);
            load_tile<256, 64 >(st + 16384, g_w1ah, f0, col, DMODEL, tid);
            load_tile<256, 64 >(st + 24576, g_w1bh, f0, col, DMODEL, tid);
        }
        CP_COMMIT();

        uint32_t ab  = sb + (c % 3) * G1_STAGE;
        uint32_t bab = ab + 16384;
        uint32_t bbb = ab + 24576;
#pragma unroll
        for (int ks = 0; ks < 4; ++ks) {
            uint32_t afr[2][4], bfa[2][4], bfb[2][4];
#pragma unroll
            for (int i = 0; i < 2; ++i)
                ldsm4(afr[i], tile_addr(ab, wm * 32 + i * 16 + lr, ks * 2 + lc));
#pragma unroll
            for (int q = 0; q < 2; ++q) {
                ldsm4(bfa[q], tile_addr(bab, wn * 32 + q * 16 + lr, ks * 2 + lc));
                ldsm4(bfb[q], tile_addr(bbb, wn * 32 + q * 16 + lr, ks * 2 + lc));
            }
#pragma unroll
            for (int i = 0; i < 2; ++i)
#pragma unroll
                for (int j = 0; j < 4; ++j) {
                    int q = j >> 1, s = j & 1;
                    mma16816(acca[i][j], afr[i], bfa[q][s], bfa[q][s + 2]);
                    mma16816(accb[i][j], afr[i], bfb[q][s], bfb[q][s + 2]);
                }
        }
    }

    // ---- epilogue: bias + InnerNet (scalar), write fp16 act ----
    const float bi2v = sp[256];
    const int g = lane >> 2, tg = lane & 3;
#pragma unroll
    for (int i = 0; i < 2; ++i) {
        float av[16], bv[16], acc[16];
#pragma unroll
        for (int j = 0; j < 4; ++j) {
            int cb = wn * 32 + j * 8 + tg * 2;
#pragma unroll
            for (int e = 0; e < 4; ++e) {
                int idx = j * 4 + e;
                int col = cb + (e & 1);
                av[idx]  = acca[i][j][e] + sp[col];
                bv[idx]  = accb[i][j][e] + sp[64 + col];
                acc[idx] = bi2v;
            }
        }
#pragma unroll 1
        for (int h = 0; h < HH; ++h) {
            float w0 = sp[128 + 2 * h], w1 = sp[129 + 2 * h];
            float cb = sp[192 + h],     vv = sp[224 + h];
#pragma unroll
            for (int idx = 0; idx < 16; ++idx) {
                float t = fmaf(av[idx], w0, cb);
                t = fmaf(bv[idx], w1, t);
                t = fmaxf(t, 0.0f);
                acc[idx] = fmaf(t, vv, acc[idx]);
            }
        }
        int rowg = m0 + wm * 32 + i * 16 + g;
#pragma unroll
        for (int j = 0; j < 4; ++j) {
            int col = f0 + wn * 32 + j * 8 + tg * 2;
            *(uint32_t*)&g_act[(size_t)rowg * DFF + col]       = pack2(acc[j * 4 + 0], acc[j * 4 + 1]);
            *(uint32_t*)&g_act[(size_t)(rowg + 8) * DFF + col] = pack2(acc[j * 4 + 2], acc[j * 4 + 3]);
        }
    }
}

// =====================================================================
// Kernel 2: out = act @ W2^T + b2   (fp16 in, fp32 out)
// CTA tile 128 tokens x 128 d_model. 256 threads, 2x4 warp grid, 64x32 warp tiles.
// 3-stage cp.async pipeline, single __syncthreads per K-chunk, occ 2.
// =====================================================================
__global__ void __launch_bounds__(256, 2) gemm2_kernel(
    const float* __restrict__ b2, float* __restrict__ out)
{
    extern __shared__ char smem[];
    uint32_t sb = s2u(smem);
    int tid = threadIdx.x, lane = tid & 31, wid = tid >> 5;
    int wm = wid >> 2, wn = wid & 3;          // 2x4 warp grid
    int n0 = blockIdx.x * 128;                // d_model tile
    int m0 = blockIdx.y * 128;                // token tile

    float* sp = (float*)(smem + G2_PAR);
    if (tid < 128) sp[tid] = b2[n0 + tid];

#pragma unroll
    for (int s = 0; s < 2; ++s) {
        uint32_t st = sb + s * G2_STAGE;
        load_tile<256, 128>(st,         g_act, m0, s * 64, DFF, tid);
        load_tile<256, 128>(st + 16384, g_w2h, n0, s * 64, DFF, tid);
        CP_COMMIT();
    }

    float acc[4][4][4];
#pragma unroll
    for (int i = 0; i < 4; ++i)
#pragma unroll
        for (int j = 0; j < 4; ++j)
#pragma unroll
            for (int e = 0; e < 4; ++e) acc[i][j][e] = 0.f;

    const int lr = lane & 15, lc = lane >> 4;
    constexpr int NCH = DFF / 64;             // 64 K-chunks
    for (int c = 0; c < NCH; ++c) {
        CP_WAIT_1();          // chunk c resident
        __syncthreads();      // all warps done reading stage (c-1)%3
        if (c + 2 < NCH) {
            uint32_t st = sb + ((c + 2) % 3) * G2_STAGE;
            int col = (c + 2) * 64;
            load_tile<256, 128>(st,         g_act, m0, col, DFF, tid);
            load_tile<256, 128>(st + 16384, g_w2h, n0, col, DFF, tid);
        }
        CP_COMMIT();

        uint32_t ab = sb + (c % 3) * G2_STAGE;
        uint32_t bb = ab + 16384;
#pragma unroll
        for (int ks = 0; ks < 4; ++ks) {
            uint32_t afr[4][4], bf[2][4];
#pragma unroll
            for (int i = 0; i < 4; ++i)
                ldsm4(afr[i], tile_addr(ab, wm * 64 + i * 16 + lr, ks * 2 + lc));
#pragma unroll
            for (int q = 0; q < 2; ++q)
                ldsm4(bf[q], tile_addr(bb, wn * 32 + q * 16 + lr, ks * 2 + lc));
#pragma unroll
            for (int i = 0; i < 4; ++i)
#pragma unroll
                for (int j = 0; j < 4; ++j) {
                    int q = j >> 1, s = j & 1;
                    mma16816(acc[i][j], afr[i], bf[q][s], bf[q][s + 2]);
                }
        }
    }

    const int g = lane >> 2, tg = lane & 3;
#pragma unroll
    for (int i = 0; i < 4; ++i) {
        int rowg = m0 + wm * 64 + i * 16 + g;
#pragma unroll
        for (int j = 0; j < 4; ++j) {
            int cb = wn * 32 + j * 8 + tg * 2;
            float2 v0 = make_float2(acc[i][j][0] + sp[cb], acc[i][j][1] + sp[cb + 1]);
            float2 v1 = make_float2(acc[i][j][2] + sp[cb], acc[i][j][3] + sp[cb + 1]);
            *(float2*)&out[(size_t)rowg * DMODEL + n0 + cb]       = v0;
            *(float2*)&out[(size_t)(rowg + 8) * DMODEL + n0 + cb] = v1;
        }
    }
}

// =====================================================================
// launch
// =====================================================================
extern "C" void kernel_launch(void* const* d_in, const int* in_sizes, int n_in,
                              void* d_out, int out_size)
{
    const float* x   = (const float*)d_in[0];
    const float* W1a = (const float*)d_in[1];
    const float* b1a = (const float*)d_in[2];
    const float* W1b = (const float*)d_in[3];
    const float* b1b = (const float*)d_in[4];
    const float* Wi1 = (const float*)d_in[5];
    const float* bi1 = (const float*)d_in[6];
    const float* Wi2 = (const float*)d_in[7];
    const float* bi2 = (const float*)d_in[8];
    const float* W2  = (const float*)d_in[9];
    const float* b2  = (const float*)d_in[10];
    float* out = (float*)d_out;

    cudaFuncSetAttribute(gemm1_kernel, cudaFuncAttributeMaxDynamicSharedMemorySize, SMEM1_TOTAL);
    cudaFuncSetAttribute(gemm2_kernel, cudaFuncAttributeMaxDynamicSharedMemorySize, SMEM2_TOTAL);

    convert_kernel<<<4096, 256>>>((const float4*)x, (const float4*)W1a,
                                  (const float4*)W1b, (const float4*)W2);
    gemm1_kernel<<<dim3(DFF / 64, NTOK / 128), 256, SMEM1_TOTAL>>>(b1a, b1b, Wi1, bi1, Wi2, bi2);
    gemm2_kernel<<<dim3(DMODEL / 128, NTOK / 128), 256, SMEM2_TOTAL>>>(b2, out);
}

// round 7
// speedup vs baseline: 1.1990x; 1.0943x over previous
#include <cuda_runtime.h>
#include <cuda_fp16.h>
#include <cstdint>

#define DI __device__ __forceinline__

// ---------------- problem constants (fixed shapes) ----------------
constexpr int NTOK   = 4096;   // B*S = 2*2048
constexpr int DMODEL = 1024;
constexpr int DFF    = 4096;
constexpr int HH     = 32;

// ---------------- scratch (device globals; no allocs allowed) ----------------
__device__ __align__(16) __half g_xh  [NTOK * DMODEL];      // 8 MB
__device__ __align__(16) __half g_w1ah[DFF  * DMODEL];      // 8 MB
__device__ __align__(16) __half g_w1bh[DFF  * DMODEL];      // 8 MB
__device__ __align__(16) __half g_w2h [DMODEL * DFF];       // 8 MB
__device__ __align__(16) __half g_act [(size_t)NTOK * DFF]; // 32 MB

// ---------------- PTX helpers ----------------
DI uint32_t s2u(const void* p) {
    uint32_t a;
    asm("{ .reg .u64 t; cvta.to.shared.u64 t, %1; cvt.u32.u64 %0, t; }"
        : "=r"(a) : "l"(p));
    return a;
}

#define CP_COMMIT() asm volatile("cp.async.commit_group;" ::: "memory")
#define CP_WAIT_1() asm volatile("cp.async.wait_group 1;" ::: "memory")

DI void cp16(uint32_t sdst, const void* gsrc) {
    asm volatile("cp.async.cg.shared.global [%0], [%1], 16;"
                 :: "r"(sdst), "l"(__cvta_generic_to_global(gsrc)) : "memory");
}

DI void ldsm4(uint32_t r[4], uint32_t addr) {
    asm volatile("ldmatrix.sync.aligned.m8n8.x4.shared.b16 {%0,%1,%2,%3}, [%4];"
                 : "=r"(r[0]), "=r"(r[1]), "=r"(r[2]), "=r"(r[3]) : "r"(addr));
}

DI void mma16816(float c[4], const uint32_t a[4], uint32_t b0, uint32_t b1) {
    asm volatile(
        "mma.sync.aligned.m16n8k16.row.col.f32.f16.f16.f32 "
        "{%0,%1,%2,%3}, {%4,%5,%6,%7}, {%8,%9}, {%0,%1,%2,%3};"
        : "+f"(c[0]), "+f"(c[1]), "+f"(c[2]), "+f"(c[3])
        : "r"(a[0]), "r"(a[1]), "r"(a[2]), "r"(a[3]), "r"(b0), "r"(b1));
}

// SW128 swizzled address inside a ROWS x 128-byte tile.
DI uint32_t tile_addr(uint32_t base, int row, int chunk) {
    return base + row * 128 + (((chunk) ^ (row & 7)) << 4);
}

// Load a ROWS x 64-fp16 (128B/row) tile into SW128-swizzled SMEM via cp.async.
template <int NT, int ROWS>
DI void load_tile(uint32_t sdst, const __half* g, int row0, int col0, int ldk, int tid) {
#pragma unroll
    for (int i = 0; i < ROWS * 8 / NT; ++i) {
        int idx = tid + i * NT;
        int r = idx >> 3, c = idx & 7;
        uint32_t off = (uint32_t)(r * 128) + (uint32_t)(((c ^ (r & 7)) << 4));
        cp16(sdst + off, g + (size_t)(row0 + r) * ldk + col0 + c * 8);
    }
}

DI uint32_t pack2(float a, float b) {
    __half2 h = __floats2half2_rn(a, b);
    return reinterpret_cast<uint32_t&>(h);
}

DI __half2 u2h(uint32_t u) { return reinterpret_cast<__half2&>(u); }
DI uint32_t h2u(__half2 h) { return reinterpret_cast<uint32_t&>(h); }

// ---------------- SMEM layouts ----------------
// gemm1: stage = A(16K for 128 rows) + Ba(8K for 64 rows) + Bb(8K) = 32K, 3 stages
constexpr int G1_STAGE  = 32768;
constexpr int G1_NSTG   = 3;
constexpr int G1_PAR    = G1_NSTG * G1_STAGE;     // 98304
constexpr int SMEM1_TOTAL = G1_PAR + 2048;        // 100352 -> 2 CTAs/SM
// gemm2: stage = A(16K) + B(16K) = 32K, 3 stages
constexpr int G2_STAGE  = 32768;
constexpr int G2_NSTG   = 3;
constexpr int G2_PAR    = G2_NSTG * G2_STAGE;     // 98304
constexpr int SMEM2_TOTAL = G2_PAR + 512;         // 98816 (occ 2)

// =====================================================================
// Kernel 0: fp32 -> fp16 conversion of x, W1a, W1b, W2
// =====================================================================
__global__ void __launch_bounds__(256) convert_kernel(
    const float4* __restrict__ x, const float4* __restrict__ w1a,
    const float4* __restrict__ w1b, const float4* __restrict__ w2)
{
    int i = blockIdx.x * 256 + threadIdx.x;   // 4096*256 = 2^20 float4s per array
    float4 v;
    v = x[i];   ((uint2*)g_xh)[i]   = make_uint2(pack2(v.x, v.y), pack2(v.z, v.w));
    v = w1a[i]; ((uint2*)g_w1ah)[i] = make_uint2(pack2(v.x, v.y), pack2(v.z, v.w));
    v = w1b[i]; ((uint2*)g_w1bh)[i] = make_uint2(pack2(v.x, v.y), pack2(v.z, v.w));
    v = w2[i];  ((uint2*)g_w2h)[i]  = make_uint2(pack2(v.x, v.y), pack2(v.z, v.w));
}

// =====================================================================
// Kernel 1: fused GEMM1 (a & b projections) + InnerNet -> fp16 act
// CTA tile 128 tokens x 64 ff. 256 threads, 4x2 warp grid, 32x32 warp tiles.
// 3-stage cp.async pipeline, occupancy 2. InnerNet epilogue in packed fp16
// (half2): 2 elements per lane-instruction, two interleaved accumulators
// (even/odd h) to bound fp16 accumulation error.
// =====================================================================
__global__ void __launch_bounds__(256, 2) gemm1_kernel(
    const float* __restrict__ b1a, const float* __restrict__ b1b,
    const float* __restrict__ wi1, const float* __restrict__ bi1,
    const float* __restrict__ wi2, const float* __restrict__ bi2)
{
    extern __shared__ char smem[];
    uint32_t sb = s2u(smem);
    int tid = threadIdx.x, lane = tid & 31, wid = tid >> 5;
    int wm = wid & 3, wn = wid >> 2;          // 4x2 warp grid, 32x32 tiles
    int f0 = blockIdx.x * 64;                 // d_ff tile
    int m0 = blockIdx.y * 128;                // token tile

    // ---- params -> smem ----
    // sp[0..63] bias_a (f32), sp[64..127] bias_b (f32)
    // phu[h*4 + 0..3] = half2{w0,w0}, {w1,w1}, {cb,cb}, {v,v}  (128 u32)
    // phu[128] = half2{bi2,bi2}
    float*    sp  = (float*)(smem + G1_PAR);
    uint32_t* phu = (uint32_t*)(smem + G1_PAR + 512);
    if (tid < 64) { sp[tid] = b1a[f0 + tid]; sp[64 + tid] = b1b[f0 + tid]; }
    else if (tid < 96) {
        int h = tid - 64;
        phu[h * 4 + 0] = pack2(wi1[2 * h],     wi1[2 * h]);
        phu[h * 4 + 1] = pack2(wi1[2 * h + 1], wi1[2 * h + 1]);
        phu[h * 4 + 2] = pack2(bi1[h],         bi1[h]);
        phu[h * 4 + 3] = pack2(wi2[h],         wi2[h]);
    } else if (tid == 96) {
        phu[128] = pack2(bi2[0], bi2[0]);
    }

    // ---- prologue: chunks 0,1 into stages 0,1 ----
#pragma unroll
    for (int s = 0; s < 2; ++s) {
        uint32_t st = sb + s * G1_STAGE;
        int col = s * 64;
        load_tile<256, 128>(st,         g_xh,   m0, col, DMODEL, tid);
        load_tile<256, 64 >(st + 16384, g_w1ah, f0, col, DMODEL, tid);
        load_tile<256, 64 >(st + 24576, g_w1bh, f0, col, DMODEL, tid);
        CP_COMMIT();
    }

    float acca[2][4][4], accb[2][4][4];
#pragma unroll
    for (int i = 0; i < 2; ++i)
#pragma unroll
        for (int j = 0; j < 4; ++j)
#pragma unroll
            for (int e = 0; e < 4; ++e) { acca[i][j][e] = 0.f; accb[i][j][e] = 0.f; }

    const int lr = lane & 15, lc = lane >> 4;
    constexpr int NCH = DMODEL / 64;          // 16 K-chunks
    for (int c = 0; c < NCH; ++c) {
        CP_WAIT_1();          // chunk c resident (c+1 may be in flight)
        __syncthreads();      // all warps finished reading stage (c-1)%3
        if (c + 2 < NCH) {
            uint32_t st = sb + ((c + 2) % 3) * G1_STAGE;
            int col = (c + 2) * 64;
            load_tile<256, 128>(st,         g_xh,   m0, col, DMODEL, tid);
            load_tile<256, 64 >(st + 16384, g_w1ah, f0, col, DMODEL, tid);
            load_tile<256, 64 >(st + 24576, g_w1bh, f0, col, DMODEL, tid);
        }
        CP_COMMIT();

        uint32_t ab  = sb + (c % 3) * G1_STAGE;
        uint32_t bab = ab + 16384;
        uint32_t bbb = ab + 24576;
#pragma unroll
        for (int ks = 0; ks < 4; ++ks) {
            uint32_t afr[2][4], bfa[2][4], bfb[2][4];
#pragma unroll
            for (int i = 0; i < 2; ++i)
                ldsm4(afr[i], tile_addr(ab, wm * 32 + i * 16 + lr, ks * 2 + lc));
#pragma unroll
            for (int q = 0; q < 2; ++q) {
                ldsm4(bfa[q], tile_addr(bab, wn * 32 + q * 16 + lr, ks * 2 + lc));
                ldsm4(bfb[q], tile_addr(bbb, wn * 32 + q * 16 + lr, ks * 2 + lc));
            }
#pragma unroll
            for (int i = 0; i < 2; ++i)
#pragma unroll
                for (int j = 0; j < 4; ++j) {
                    int q = j >> 1, s = j & 1;
                    mma16816(acca[i][j], afr[i], bfa[q][s], bfa[q][s + 2]);
                    mma16816(accb[i][j], afr[i], bfb[q][s], bfb[q][s + 2]);
                }
        }
    }

    // ---- epilogue: bias + InnerNet in packed fp16, write fp16 act ----
    const __half2 BI2 = u2h(phu[128]);
    const __half2 Z2  = __floats2half2_rn(0.f, 0.f);
    const int g = lane >> 2, tg = lane & 3;
#pragma unroll
    for (int i = 0; i < 2; ++i) {
        // Build half2 element-pairs: p = j*2 + {0 (row g), 1 (row g+8)}
        __half2 A2[8], B2[8], acc0[8], acc1[8];
#pragma unroll
        for (int j = 0; j < 4; ++j) {
            int cb = wn * 32 + j * 8 + tg * 2;
            float ba0 = sp[cb], ba1 = sp[cb + 1];
            float bb0 = sp[64 + cb], bb1 = sp[64 + cb + 1];
            A2[j * 2]     = __floats2half2_rn(acca[i][j][0] + ba0, acca[i][j][1] + ba1);
            A2[j * 2 + 1] = __floats2half2_rn(acca[i][j][2] + ba0, acca[i][j][3] + ba1);
            B2[j * 2]     = __floats2half2_rn(accb[i][j][0] + bb0, accb[i][j][1] + bb1);
            B2[j * 2 + 1] = __floats2half2_rn(accb[i][j][2] + bb0, accb[i][j][3] + bb1);
            acc0[j * 2] = Z2; acc0[j * 2 + 1] = Z2;
            acc1[j * 2] = Z2; acc1[j * 2 + 1] = Z2;
        }
#pragma unroll 1
        for (int hh = 0; hh < HH / 2; ++hh) {
            __half2 W0e = u2h(phu[hh * 8 + 0]), W1e = u2h(phu[hh * 8 + 1]);
            __half2 CBe = u2h(phu[hh * 8 + 2]), VHe = u2h(phu[hh * 8 + 3]);
            __half2 W0o = u2h(phu[hh * 8 + 4]), W1o = u2h(phu[hh * 8 + 5]);
            __half2 CBo = u2h(phu[hh * 8 + 6]), VHo = u2h(phu[hh * 8 + 7]);
#pragma unroll
            for (int p = 0; p < 8; ++p) {
                __half2 t0 = __hfma2(A2[p], W0e, __hfma2(B2[p], W1e, CBe));
                acc0[p] = __hfma2(__hmax2(t0, Z2), VHe, acc0[p]);
                __half2 t1 = __hfma2(A2[p], W0o, __hfma2(B2[p], W1o, CBo));
                acc1[p] = __hfma2(__hmax2(t1, Z2), VHo, acc1[p]);
            }
        }
        int rowg = m0 + wm * 32 + i * 16 + g;
#pragma unroll
        for (int j = 0; j < 4; ++j) {
            int col = f0 + wn * 32 + j * 8 + tg * 2;
            __half2 s0 = __hadd2(__hadd2(acc0[j * 2],     acc1[j * 2]),     BI2);
            __half2 s1 = __hadd2(__hadd2(acc0[j * 2 + 1], acc1[j * 2 + 1]), BI2);
            *(uint32_t*)&g_act[(size_t)rowg * DFF + col]       = h2u(s0);
            *(uint32_t*)&g_act[(size_t)(rowg + 8) * DFF + col] = h2u(s1);
        }
    }
}

// =====================================================================
// Kernel 2: out = act @ W2^T + b2   (fp16 in, fp32 out)
// CTA tile 128 tokens x 128 d_model. 256 threads, 2x4 warp grid, 64x32 warp tiles.
// 3-stage cp.async pipeline, single __syncthreads per K-chunk, occ 2.
// =====================================================================
__global__ void __launch_bounds__(256, 2) gemm2_kernel(
    const float* __restrict__ b2, float* __restrict__ out)
{
    extern __shared__ char smem[];
    uint32_t sb = s2u(smem);
    int tid = threadIdx.x, lane = tid & 31, wid = tid >> 5;
    int wm = wid >> 2, wn = wid & 3;          // 2x4 warp grid
    int n0 = blockIdx.x * 128;                // d_model tile
    int m0 = blockIdx.y * 128;                // token tile

    float* sp = (float*)(smem + G2_PAR);
    if (tid < 128) sp[tid] = b2[n0 + tid];

#pragma unroll
    for (int s = 0; s < 2; ++s) {
        uint32_t st = sb + s * G2_STAGE;
        load_tile<256, 128>(st,         g_act, m0, s * 64, DFF, tid);
        load_tile<256, 128>(st + 16384, g_w2h, n0, s * 64, DFF, tid);
        CP_COMMIT();
    }

    float acc[4][4][4];
#pragma unroll
    for (int i = 0; i < 4; ++i)
#pragma unroll
        for (int j = 0; j < 4; ++j)
#pragma unroll
            for (int e = 0; e < 4; ++e) acc[i][j][e] = 0.f;

    const int lr = lane & 15, lc = lane >> 4;
    constexpr int NCH = DFF / 64;             // 64 K-chunks
    for (int c = 0; c < NCH; ++c) {
        CP_WAIT_1();          // chunk c resident
        __syncthreads();      // all warps done reading stage (c-1)%3
        if (c + 2 < NCH) {
            uint32_t st = sb + ((c + 2) % 3) * G2_STAGE;
            int col = (c + 2) * 64;
            load_tile<256, 128>(st,         g_act, m0, col, DFF, tid);
            load_tile<256, 128>(st + 16384, g_w2h, n0, col, DFF, tid);
        }
        CP_COMMIT();

        uint32_t ab = sb + (c % 3) * G2_STAGE;
        uint32_t bb = ab + 16384;
#pragma unroll
        for (int ks = 0; ks < 4; ++ks) {
            uint32_t afr[4][4], bf[2][4];
#pragma unroll
            for (int i = 0; i < 4; ++i)
                ldsm4(afr[i], tile_addr(ab, wm * 64 + i * 16 + lr, ks * 2 + lc));
#pragma unroll
            for (int q = 0; q < 2; ++q)
                ldsm4(bf[q], tile_addr(bb, wn * 32 + q * 16 + lr, ks * 2 + lc));
#pragma unroll
            for (int i = 0; i < 4; ++i)
#pragma unroll
                for (int j = 0; j < 4; ++j) {
                    int q = j >> 1, s = j & 1;
                    mma16816(acc[i][j], afr[i], bf[q][s], bf[q][s + 2]);
                }
        }
    }

    const int g = lane >> 2, tg = lane & 3;
#pragma unroll
    for (int i = 0; i < 4; ++i) {
        int rowg = m0 + wm * 64 + i * 16 + g;
#pragma unroll
        for (int j = 0; j < 4; ++j) {
            int cb = wn * 32 + j * 8 + tg * 2;
            float2 v0 = make_float2(acc[i][j][0] + sp[cb], acc[i][j][1] + sp[cb + 1]);
            float2 v1 = make_float2(acc[i][j][2] + sp[cb], acc[i][j][3] + sp[cb + 1]);
            *(float2*)&out[(size_t)rowg * DMODEL + n0 + cb]       = v0;
            *(float2*)&out[(size_t)(rowg + 8) * DMODEL + n0 + cb] = v1;
        }
    }
}

// =====================================================================
// launch
// =====================================================================
extern "C" void kernel_launch(void* const* d_in, const int* in_sizes, int n_in,
                              void* d_out, int out_size)
{
    const float* x   = (const float*)d_in[0];
    const float* W1a = (const float*)d_in[1];
    const float* b1a = (const float*)d_in[2];
    const float* W1b = (const float*)d_in[3];
    const float* b1b = (const float*)d_in[4];
    const float* Wi1 = (const float*)d_in[5];
    const float* bi1 = (const float*)d_in[6];
    const float* Wi2 = (const float*)d_in[7];
    const float* bi2 = (const float*)d_in[8];
    const float* W2  = (const float*)d_in[9];
    const float* b2  = (const float*)d_in[10];
    float* out = (float*)d_out;

    cudaFuncSetAttribute(gemm1_kernel, cudaFuncAttributeMaxDynamicSharedMemorySize, SMEM1_TOTAL);
    cudaFuncSetAttribute(gemm2_kernel, cudaFuncAttributeMaxDynamicSharedMemorySize, SMEM2_TOTAL);

    convert_kernel<<<4096, 256>>>((const float4*)x, (const float4*)W1a,
                                  (const float4*)W1b, (const float4*)W2);
    gemm1_kernel<<<dim3(DFF / 64, NTOK / 128), 256, SMEM1_TOTAL>>>(b1a, b1b, Wi1, bi1, Wi2, bi2);
    gemm2_kernel<<<dim3(DMODEL / 128, NTOK / 128), 256, SMEM2_TOTAL>>>(b2, out);
}